// round 2
// baseline (speedup 1.0000x reference)
#include <cuda_runtime.h>
#include <math.h>

#define NN 50000
#define NE 1600000
#define CH 128
#define FE 50
#define FEP 52          // padded basis width (mult of 4, zero-filled)
#define TS 132          // padded row stride for 128-float rows (mult of 4)

// Device-global scratch (allocation-free rule: __device__ arrays are allowed)
__device__ float g_h[(size_t)NN * CH];
__device__ float g_agg[(size_t)NN * CH];

__device__ __forceinline__ float ssp(float x) {
    return fmaxf(x, 0.0f) + log1pf(__expf(-fabsf(x))) - 0.69314718055994530942f;
}

__device__ __forceinline__ void red_add_v4(float* addr, float4 v) {
    asm volatile("red.global.add.v4.f32 [%0], {%1,%2,%3,%4};"
                 :: "l"(addr), "f"(v.x), "f"(v.y), "f"(v.z), "f"(v.w)
                 : "memory");
}

#define FMA8(ar, av, w0, w1)                 \
    ar[0] = fmaf(av, w0.x, ar[0]);           \
    ar[1] = fmaf(av, w0.y, ar[1]);           \
    ar[2] = fmaf(av, w0.z, ar[2]);           \
    ar[3] = fmaf(av, w0.w, ar[3]);           \
    ar[4] = fmaf(av, w1.x, ar[4]);           \
    ar[5] = fmaf(av, w1.y, ar[5]);           \
    ar[6] = fmaf(av, w1.z, ar[6]);           \
    ar[7] = fmaf(av, w1.w, ar[7]);

// ---------------------------------------------------------------------------
__global__ void zero_agg_kernel() {
    size_t i = (size_t)blockIdx.x * blockDim.x + threadIdx.x;
    size_t stride = (size_t)gridDim.x * blockDim.x;
    float4* p = reinterpret_cast<float4*>(g_agg);
    const size_t n4 = (size_t)NN * CH / 4;
    float4 z = make_float4(0.f, 0.f, 0.f, 0.f);
    for (; i < n4; i += stride) p[i] = z;
}

// ---------------------------------------------------------------------------
// h = features @ W_lin^T.  512 threads, 128-node tile, 4x8 micro-tile.
// ---------------------------------------------------------------------------
__global__ __launch_bounds__(512, 1)
void node_linear_kernel(const float* __restrict__ feat, const float* __restrict__ W)
{
    extern __shared__ float sm[];
    float* Wt = sm;               // [128][TS]  Wt[k*TS+c] = W[c*128+k]
    float* fS = sm + CH * TS;     // [128][TS]
    const int tid = threadIdx.x;
    const int n0 = blockIdx.x * 128;

    for (int i = tid; i < CH * CH; i += 512) {
        int c = i >> 7, k = i & 127;
        Wt[k * TS + c] = W[i];
    }
    for (int i = tid; i < 128 * (CH / 4); i += 512) {
        int r = i >> 5, k4 = i & 31;
        int n = n0 + r;
        float4 v = make_float4(0.f, 0.f, 0.f, 0.f);
        if (n < NN) v = reinterpret_cast<const float4*>(feat)[(size_t)n * 32 + k4];
        *reinterpret_cast<float4*>(fS + r * TS + k4 * 4) = v;
    }
    __syncthreads();

    const int ei = tid >> 4;          // 0..31 (4 rows each)
    const int c0 = (tid & 15) * 8;

    float acc[4][8];
    #pragma unroll
    for (int r = 0; r < 4; r++)
        #pragma unroll
        for (int j = 0; j < 8; j++) acc[r][j] = 0.f;

    #pragma unroll 4
    for (int k4 = 0; k4 < CH; k4 += 4) {
        float4 av[4];
        #pragma unroll
        for (int r = 0; r < 4; r++)
            av[r] = *reinterpret_cast<const float4*>(fS + (ei * 4 + r) * TS + k4);
        #pragma unroll
        for (int kk = 0; kk < 4; kk++) {
            float4 w0 = *reinterpret_cast<const float4*>(Wt + (k4 + kk) * TS + c0);
            float4 w1 = *reinterpret_cast<const float4*>(Wt + (k4 + kk) * TS + c0 + 4);
            #pragma unroll
            for (int r = 0; r < 4; r++) {
                float a = reinterpret_cast<const float*>(&av[r])[kk];
                FMA8(acc[r], a, w0, w1);
            }
        }
    }

    #pragma unroll
    for (int r = 0; r < 4; r++) {
        int n = n0 + ei * 4 + r;
        if (n < NN) {
            float* dst = g_h + (size_t)n * CH + c0;
            *reinterpret_cast<float4*>(dst)     = make_float4(acc[r][0], acc[r][1], acc[r][2], acc[r][3]);
            *reinterpret_cast<float4*>(dst + 4) = make_float4(acc[r][4], acc[r][5], acc[r][6], acc[r][7]);
        }
    }
}

// ---------------------------------------------------------------------------
// Fused edge kernel. 512 threads, 128 edges/block, 4x8 micro-tile.
// ---------------------------------------------------------------------------
__global__ __launch_bounds__(512, 1)
void edge_kernel(const float* __restrict__ dist,
                 const float* __restrict__ Wf1, const float* __restrict__ bf1,
                 const float* __restrict__ Wf2, const float* __restrict__ bf2,
                 const int* __restrict__ senders, const int* __restrict__ receivers)
{
    extern __shared__ float sm[];
    float* Wf1s  = sm;                        // [FEP][128] = 6656
    float* Wf2s  = Wf1s + FEP * CH;           // [128][128] = 16384
    float* bf1s  = Wf2s + CH * CH;            // 128
    float* bf2s  = bf1s + CH;                 // 128
    float* basis = bf2s + CH;                 // [128][FEP] = 6656
    float* t1    = basis + 128 * FEP;         // [128][TS]  = 16896

    const int tid = threadIdx.x;
    const int e0 = blockIdx.x * 128;

    // weights: pad rows 50,51 of Wf1 with zeros (a=0 there, keep 0*w finite)
    for (int i = tid; i < FEP * CH; i += 512) {
        int f = i >> 7;
        Wf1s[i] = (f < FE) ? Wf1[i] : 0.f;
    }
    for (int i = tid; i < CH * CH; i += 512) Wf2s[i] = Wf2[i];
    if (tid < CH) { bf1s[tid] = bf1[tid]; bf2s[tid] = bf2[tid]; }

    // Gaussian smearing into padded [128][FEP] (pad cols zero)
    const float delta = 5.0f / 49.0f;
    const float coef  = (49.0f * 49.0f) / 50.0f;
    for (int i = tid; i < 128 * FEP; i += 512) {
        int e = i / FEP, f = i - e * FEP;
        float v = 0.f;
        if (f < FE) {
            float r = dist[e0 + e];
            float d = r - delta * (float)f;
            v = __expf(-coef * d * d);
        }
        basis[i] = v;
    }
    __syncthreads();

    const int ei = tid >> 4;
    const int c0 = (tid & 15) * 8;

    // ---- stage 1: t1 = ssp(basis @ Wf1 + bf1) ----
    float acc[4][8];
    #pragma unroll
    for (int r = 0; r < 4; r++)
        #pragma unroll
        for (int j = 0; j < 8; j++) acc[r][j] = bf1s[c0 + j];

    #pragma unroll 2
    for (int f4 = 0; f4 < FEP; f4 += 4) {
        float4 av[4];
        #pragma unroll
        for (int r = 0; r < 4; r++)
            av[r] = *reinterpret_cast<const float4*>(basis + (ei * 4 + r) * FEP + f4);
        #pragma unroll
        for (int kk = 0; kk < 4; kk++) {
            float4 w0 = *reinterpret_cast<const float4*>(Wf1s + (f4 + kk) * CH + c0);
            float4 w1 = *reinterpret_cast<const float4*>(Wf1s + (f4 + kk) * CH + c0 + 4);
            #pragma unroll
            for (int r = 0; r < 4; r++) {
                float a = reinterpret_cast<const float*>(&av[r])[kk];
                FMA8(acc[r], a, w0, w1);
            }
        }
    }
    #pragma unroll
    for (int r = 0; r < 4; r++) {
        float* dst = t1 + (ei * 4 + r) * TS + c0;
        *reinterpret_cast<float4*>(dst)     = make_float4(ssp(acc[r][0]), ssp(acc[r][1]), ssp(acc[r][2]), ssp(acc[r][3]));
        *reinterpret_cast<float4*>(dst + 4) = make_float4(ssp(acc[r][4]), ssp(acc[r][5]), ssp(acc[r][6]), ssp(acc[r][7]));
    }
    __syncthreads();

    // prefetch edge indices (hide L2 latency behind stage-2 math)
    int sIdx[4], rIdx[4];
    #pragma unroll
    for (int r = 0; r < 4; r++) {
        int e = e0 + ei * 4 + r;
        sIdx[r] = senders[e];
        rIdx[r] = receivers[e];
    }

    // ---- stage 2: ef = t1 @ Wf2 + bf2 ----
    #pragma unroll
    for (int r = 0; r < 4; r++)
        #pragma unroll
        for (int j = 0; j < 8; j++) acc[r][j] = bf2s[c0 + j];

    #pragma unroll 4
    for (int k4 = 0; k4 < CH; k4 += 4) {
        float4 av[4];
        #pragma unroll
        for (int r = 0; r < 4; r++)
            av[r] = *reinterpret_cast<const float4*>(t1 + (ei * 4 + r) * TS + k4);
        #pragma unroll
        for (int kk = 0; kk < 4; kk++) {
            float4 w0 = *reinterpret_cast<const float4*>(Wf2s + (k4 + kk) * CH + c0);
            float4 w1 = *reinterpret_cast<const float4*>(Wf2s + (k4 + kk) * CH + c0 + 4);
            #pragma unroll
            for (int r = 0; r < 4; r++) {
                float a = reinterpret_cast<const float*>(&av[r])[kk];
                FMA8(acc[r], a, w0, w1);
            }
        }
    }

    // ---- stage 3: gather h, multiply, scatter-add ----
    #pragma unroll
    for (int r = 0; r < 4; r++) {
        const float* hp = g_h + (size_t)sIdx[r] * CH + c0;
        float4 h0 = *reinterpret_cast<const float4*>(hp);
        float4 h1 = *reinterpret_cast<const float4*>(hp + 4);
        float4 m0 = make_float4(acc[r][0] * h0.x, acc[r][1] * h0.y,
                                acc[r][2] * h0.z, acc[r][3] * h0.w);
        float4 m1 = make_float4(acc[r][4] * h1.x, acc[r][5] * h1.y,
                                acc[r][6] * h1.z, acc[r][7] * h1.w);
        float* dst = g_agg + (size_t)rIdx[r] * CH + c0;
        red_add_v4(dst, m0);
        red_add_v4(dst + 4, m1);
    }
}

// ---------------------------------------------------------------------------
// out = ssp(agg @ Wm1 + bm1) @ Wm2 + bm2.  512 threads, 4x8 micro-tile.
// ---------------------------------------------------------------------------
__global__ __launch_bounds__(512, 1)
void out_mlp_kernel(const float* __restrict__ Wm1, const float* __restrict__ bm1,
                    const float* __restrict__ Wm2, const float* __restrict__ bm2,
                    float* __restrict__ out)
{
    extern __shared__ float sm[];
    float* Ws  = sm;                   // [128][128] (Wm1, then Wm2)
    float* bs  = Ws + CH * CH;         // 128
    float* inS = bs + CH;              // [128][TS]
    float* tS  = inS + 128 * TS;       // [128][TS]

    const int tid = threadIdx.x;
    const int n0 = blockIdx.x * 128;

    for (int i = tid; i < CH * CH; i += 512) Ws[i] = Wm1[i];
    if (tid < CH) bs[tid] = bm1[tid];
    for (int i = tid; i < 128 * (CH / 4); i += 512) {
        int r = i >> 5, k4 = i & 31;
        int n = n0 + r;
        float4 v = make_float4(0.f, 0.f, 0.f, 0.f);
        if (n < NN) v = reinterpret_cast<const float4*>(g_agg)[(size_t)n * 32 + k4];
        *reinterpret_cast<float4*>(inS + r * TS + k4 * 4) = v;
    }
    __syncthreads();

    const int ei = tid >> 4;
    const int c0 = (tid & 15) * 8;

    float acc[4][8];
    #pragma unroll
    for (int r = 0; r < 4; r++)
        #pragma unroll
        for (int j = 0; j < 8; j++) acc[r][j] = bs[c0 + j];

    #pragma unroll 4
    for (int k4 = 0; k4 < CH; k4 += 4) {
        float4 av[4];
        #pragma unroll
        for (int r = 0; r < 4; r++)
            av[r] = *reinterpret_cast<const float4*>(inS + (ei * 4 + r) * TS + k4);
        #pragma unroll
        for (int kk = 0; kk < 4; kk++) {
            float4 w0 = *reinterpret_cast<const float4*>(Ws + (k4 + kk) * CH + c0);
            float4 w1 = *reinterpret_cast<const float4*>(Ws + (k4 + kk) * CH + c0 + 4);
            #pragma unroll
            for (int r = 0; r < 4; r++) {
                float a = reinterpret_cast<const float*>(&av[r])[kk];
                FMA8(acc[r], a, w0, w1);
            }
        }
    }
    #pragma unroll
    for (int r = 0; r < 4; r++) {
        float* dst = tS + (ei * 4 + r) * TS + c0;
        *reinterpret_cast<float4*>(dst)     = make_float4(ssp(acc[r][0]), ssp(acc[r][1]), ssp(acc[r][2]), ssp(acc[r][3]));
        *reinterpret_cast<float4*>(dst + 4) = make_float4(ssp(acc[r][4]), ssp(acc[r][5]), ssp(acc[r][6]), ssp(acc[r][7]));
    }
    __syncthreads();

    for (int i = tid; i < CH * CH; i += 512) Ws[i] = Wm2[i];
    if (tid < CH) bs[tid] = bm2[tid];
    __syncthreads();

    #pragma unroll
    for (int r = 0; r < 4; r++)
        #pragma unroll
        for (int j = 0; j < 8; j++) acc[r][j] = bs[c0 + j];

    #pragma unroll 4
    for (int k4 = 0; k4 < CH; k4 += 4) {
        float4 av[4];
        #pragma unroll
        for (int r = 0; r < 4; r++)
            av[r] = *reinterpret_cast<const float4*>(tS + (ei * 4 + r) * TS + k4);
        #pragma unroll
        for (int kk = 0; kk < 4; kk++) {
            float4 w0 = *reinterpret_cast<const float4*>(Ws + (k4 + kk) * CH + c0);
            float4 w1 = *reinterpret_cast<const float4*>(Ws + (k4 + kk) * CH + c0 + 4);
            #pragma unroll
            for (int r = 0; r < 4; r++) {
                float a = reinterpret_cast<const float*>(&av[r])[kk];
                FMA8(acc[r], a, w0, w1);
            }
        }
    }

    #pragma unroll
    for (int r = 0; r < 4; r++) {
        int n = n0 + ei * 4 + r;
        if (n < NN) {
            float* dst = out + (size_t)n * CH + c0;
            *reinterpret_cast<float4*>(dst)     = make_float4(acc[r][0], acc[r][1], acc[r][2], acc[r][3]);
            *reinterpret_cast<float4*>(dst + 4) = make_float4(acc[r][4], acc[r][5], acc[r][6], acc[r][7]);
        }
    }
}

// ---------------------------------------------------------------------------
extern "C" void kernel_launch(void* const* d_in, const int* in_sizes, int n_in,
                              void* d_out, int out_size)
{
    const float* features = (const float*)d_in[0];
    const float* dist     = (const float*)d_in[1];
    const float* W_lin    = (const float*)d_in[2];
    const float* Wf1      = (const float*)d_in[3];
    const float* bf1      = (const float*)d_in[4];
    const float* Wf2      = (const float*)d_in[5];
    const float* bf2      = (const float*)d_in[6];
    const float* Wm1      = (const float*)d_in[7];
    const float* bm1      = (const float*)d_in[8];
    const float* Wm2      = (const float*)d_in[9];
    const float* bm2      = (const float*)d_in[10];
    const int*   senders   = (const int*)d_in[11];
    const int*   receivers = (const int*)d_in[12];
    float* out = (float*)d_out;

    const int smemA = (2 * CH * TS) * 4;                                           // 135168
    const int smemB = (FEP * CH + CH * CH + 2 * CH + 128 * FEP + 128 * TS) * 4;    // 187392
    const int smemC = (CH * CH + CH + 2 * 128 * TS) * 4;                           // 201216

    cudaFuncSetAttribute(node_linear_kernel, cudaFuncAttributeMaxDynamicSharedMemorySize, smemA);
    cudaFuncSetAttribute(edge_kernel,        cudaFuncAttributeMaxDynamicSharedMemorySize, smemB);
    cudaFuncSetAttribute(out_mlp_kernel,     cudaFuncAttributeMaxDynamicSharedMemorySize, smemC);

    zero_agg_kernel<<<1024, 256>>>();
    node_linear_kernel<<<(NN + 127) / 128, 512, smemA>>>(features, W_lin);
    edge_kernel<<<NE / 128, 512, smemB>>>(dist, Wf1, bf1, Wf2, bf2, senders, receivers);
    out_mlp_kernel<<<(NN + 127) / 128, 512, smemC>>>(Wm1, bm1, Wm2, bm2, out);
}

// round 4
// speedup vs baseline: 7.1723x; 7.1723x over previous
#include <cuda_runtime.h>
#include <math.h>
#include <stdint.h>

#define NN 50000
#define NE 1600000
#define CH 128
#define FE 50
#define TS 132
#define NTAB 16384              // grid intervals over [0,5]; table has NTAB+1 rows

// Device-global scratch (allocation-free rule: __device__ arrays allowed)
__device__ float g_h[(size_t)NN * CH];
__device__ float g_agg[(size_t)NN * CH];
__device__ float g_table[(size_t)(NTAB + 1) * CH];   // ef(r_i), 8.4 MB

__device__ __forceinline__ float ssp(float x) {
    return fmaxf(x, 0.0f) + log1pf(__expf(-fabsf(x))) - 0.69314718055994530942f;
}

__device__ __forceinline__ void red_add_v4(float* addr, float4 v) {
    asm volatile("red.global.add.v4.f32 [%0], {%1,%2,%3,%4};"
                 :: "l"(addr), "f"(v.x), "f"(v.y), "f"(v.z), "f"(v.w) : "memory");
}

#define FMA8(ar, av, w0, w1)                 \
    ar[0] = fmaf(av, w0.x, ar[0]);           \
    ar[1] = fmaf(av, w0.y, ar[1]);           \
    ar[2] = fmaf(av, w0.z, ar[2]);           \
    ar[3] = fmaf(av, w0.w, ar[3]);           \
    ar[4] = fmaf(av, w1.x, ar[4]);           \
    ar[5] = fmaf(av, w1.y, ar[5]);           \
    ar[6] = fmaf(av, w1.z, ar[6]);           \
    ar[7] = fmaf(av, w1.w, ar[7]);

// ---------------------------------------------------------------------------
__global__ void zero_agg_kernel() {
    size_t i = (size_t)blockIdx.x * blockDim.x + threadIdx.x;
    size_t stride = (size_t)gridDim.x * blockDim.x;
    float4* p = reinterpret_cast<float4*>(g_agg);
    const size_t n4 = (size_t)NN * CH / 4;
    float4 z = make_float4(0.f, 0.f, 0.f, 0.f);
    for (; i < n4; i += stride) p[i] = z;
}

// ---------------------------------------------------------------------------
// Build table: ef(r_i) for r_i = i * 5/NTAB, i in [0, NTAB].
// Same proven 8x8 micro-tile structure as the R1 edge kernel; 128 rows/block.
// ---------------------------------------------------------------------------
__global__ __launch_bounds__(256, 1)
void table_kernel(const float* __restrict__ Wf1, const float* __restrict__ bf1,
                  const float* __restrict__ Wf2, const float* __restrict__ bf2)
{
    extern __shared__ float sm[];
    float* Wf1s  = sm;                       // 50*128
    float* Wf2s  = Wf1s + FE * CH;           // 128*128
    float* bf1s  = Wf2s + CH * CH;           // 128
    float* bf2s  = bf1s + CH;                // 128
    float* basis = bf2s + CH;                // 128*53
    float* t1    = basis + 128 * 53;         // 128*130

    const int tid = threadIdx.x;
    const int e0 = blockIdx.x * 128;
    const float H = 5.0f / (float)NTAB;

    for (int i = tid; i < FE * CH; i += 256) Wf1s[i] = Wf1[i];
    for (int i = tid; i < CH * CH; i += 256) Wf2s[i] = Wf2[i];
    if (tid < CH) { bf1s[tid] = bf1[tid]; bf2s[tid] = bf2[tid]; }

    const float delta = 5.0f / 49.0f;
    const float coef  = 2401.0f / 50.0f;     // 1/(2*delta^2)
    for (int i = tid; i < 128 * FE; i += 256) {
        int e = i / FE, f = i - e * FE;
        float r = (float)(e0 + e) * H;
        float d = r - delta * (float)f;
        basis[e * 53 + f] = __expf(-coef * d * d);
    }
    __syncthreads();

    const int ei = tid >> 4;
    const int c0 = (tid & 15) * 8;

    float acc[8][8];
    #pragma unroll
    for (int r = 0; r < 8; r++)
        #pragma unroll
        for (int j = 0; j < 8; j++) acc[r][j] = bf1s[c0 + j];

    #pragma unroll 2
    for (int f = 0; f < FE; f++) {
        float a[8];
        #pragma unroll
        for (int r = 0; r < 8; r++) a[r] = basis[(ei * 8 + r) * 53 + f];
        float4 w0 = *reinterpret_cast<const float4*>(Wf1s + f * CH + c0);
        float4 w1 = *reinterpret_cast<const float4*>(Wf1s + f * CH + c0 + 4);
        #pragma unroll
        for (int r = 0; r < 8; r++) { FMA8(acc[r], a[r], w0, w1); }
    }
    #pragma unroll
    for (int r = 0; r < 8; r++)
        #pragma unroll
        for (int j = 0; j < 8; j++)
            t1[(ei * 8 + r) * 130 + c0 + j] = ssp(acc[r][j]);
    __syncthreads();

    #pragma unroll
    for (int r = 0; r < 8; r++)
        #pragma unroll
        for (int j = 0; j < 8; j++) acc[r][j] = bf2s[c0 + j];

    #pragma unroll 2
    for (int k = 0; k < CH; k++) {
        float a[8];
        #pragma unroll
        for (int r = 0; r < 8; r++) a[r] = t1[(ei * 8 + r) * 130 + k];
        float4 w0 = *reinterpret_cast<const float4*>(Wf2s + k * CH + c0);
        float4 w1 = *reinterpret_cast<const float4*>(Wf2s + k * CH + c0 + 4);
        #pragma unroll
        for (int r = 0; r < 8; r++) { FMA8(acc[r], a[r], w0, w1); }
    }

    #pragma unroll
    for (int r = 0; r < 8; r++) {
        int row = e0 + ei * 8 + r;
        if (row <= NTAB) {
            float* dst = g_table + (size_t)row * CH + c0;
            *reinterpret_cast<float4*>(dst)     = make_float4(acc[r][0], acc[r][1], acc[r][2], acc[r][3]);
            *reinterpret_cast<float4*>(dst + 4) = make_float4(acc[r][4], acc[r][5], acc[r][6], acc[r][7]);
        }
    }
}

// ---------------------------------------------------------------------------
// h = features @ W_lin^T (R1 version: 256 threads, 8x8 micro-tile)
// ---------------------------------------------------------------------------
__global__ __launch_bounds__(256, 1)
void node_linear_kernel(const float* __restrict__ feat, const float* __restrict__ W)
{
    extern __shared__ float sm[];
    float* Wt = sm;                  // [128][TS]
    float* fS = sm + CH * TS;        // [128][130]
    const int tid = threadIdx.x;
    const int n0 = blockIdx.x * 128;

    for (int i = tid; i < CH * CH; i += 256) {
        int c = i >> 7, k = i & 127;
        Wt[k * TS + c] = W[i];
    }
    for (int i = tid; i < 128 * (CH / 4); i += 256) {
        int r = i >> 5, k4 = i & 31;
        int n = n0 + r;
        float4 v = make_float4(0.f, 0.f, 0.f, 0.f);
        if (n < NN) v = reinterpret_cast<const float4*>(feat)[(size_t)n * 32 + k4];
        float* p = fS + r * 130 + k4 * 4;
        p[0] = v.x; p[1] = v.y; p[2] = v.z; p[3] = v.w;
    }
    __syncthreads();

    const int ei = tid >> 4;
    const int c0 = (tid & 15) * 8;

    float acc[8][8];
    #pragma unroll
    for (int r = 0; r < 8; r++)
        #pragma unroll
        for (int j = 0; j < 8; j++) acc[r][j] = 0.f;

    #pragma unroll 2
    for (int k = 0; k < CH; k++) {
        float a[8];
        #pragma unroll
        for (int r = 0; r < 8; r++) a[r] = fS[(ei * 8 + r) * 130 + k];
        float4 w0 = *reinterpret_cast<const float4*>(Wt + k * TS + c0);
        float4 w1 = *reinterpret_cast<const float4*>(Wt + k * TS + c0 + 4);
        #pragma unroll
        for (int r = 0; r < 8; r++) { FMA8(acc[r], a[r], w0, w1); }
    }

    #pragma unroll
    for (int r = 0; r < 8; r++) {
        int n = n0 + ei * 8 + r;
        if (n < NN) {
            float* dst = g_h + (size_t)n * CH + c0;
            *reinterpret_cast<float4*>(dst)     = make_float4(acc[r][0], acc[r][1], acc[r][2], acc[r][3]);
            *reinterpret_cast<float4*>(dst + 4) = make_float4(acc[r][4], acc[r][5], acc[r][6], acc[r][7]);
        }
    }
}

// ---------------------------------------------------------------------------
// Edge apply: ef = lerp(table, r); msg = ef * h[sender]; agg[receiver] += msg.
// One warp per edge; lane handles 4 channels (float4). Pure L2 traffic.
// ---------------------------------------------------------------------------
__global__ __launch_bounds__(256, 8)
void edge_apply_kernel(const float* __restrict__ dist,
                       const int* __restrict__ senders,
                       const int* __restrict__ receivers)
{
    const int lane = threadIdx.x & 31;
    int warp = (blockIdx.x * blockDim.x + threadIdx.x) >> 5;
    const int nwarps = (gridDim.x * blockDim.x) >> 5;
    const float SCALE = (float)NTAB / 5.0f;

    for (int e = warp; e < NE; e += nwarps) {
        float r = __ldg(dist + e);
        int s  = __ldg(senders + e);
        int rc = __ldg(receivers + e);

        float u = r * SCALE;
        int i = (int)u;
        i = i < 0 ? 0 : (i > NTAB - 1 ? NTAB - 1 : i);
        float f = u - (float)i;

        const float4* ta = reinterpret_cast<const float4*>(g_table + (size_t)i * CH) + lane;
        float4 a = ta[0];
        float4 b = ta[CH / 4];                 // next row, same lane
        const float4* hp = reinterpret_cast<const float4*>(g_h + (size_t)s * CH) + lane;
        float4 hv = hp[0];

        float4 m;
        m.x = fmaf(f, b.x - a.x, a.x) * hv.x;
        m.y = fmaf(f, b.y - a.y, a.y) * hv.y;
        m.z = fmaf(f, b.z - a.z, a.z) * hv.z;
        m.w = fmaf(f, b.w - a.w, a.w) * hv.w;

        red_add_v4(g_agg + (size_t)rc * CH + lane * 4, m);
    }
}

// ---------------------------------------------------------------------------
// out = ssp(agg @ Wm1 + bm1) @ Wm2 + bm2 (R1 version)
// ---------------------------------------------------------------------------
__global__ __launch_bounds__(256, 1)
void out_mlp_kernel(const float* __restrict__ Wm1, const float* __restrict__ bm1,
                    const float* __restrict__ Wm2, const float* __restrict__ bm2,
                    float* __restrict__ out)
{
    extern __shared__ float sm[];
    float* Ws  = sm;
    float* bs  = Ws + CH * CH;
    float* inS = bs + CH;
    float* tS  = inS + 128 * 130;

    const int tid = threadIdx.x;
    const int n0 = blockIdx.x * 128;

    for (int i = tid; i < CH * CH; i += 256) Ws[i] = Wm1[i];
    if (tid < CH) bs[tid] = bm1[tid];
    for (int i = tid; i < 128 * (CH / 4); i += 256) {
        int r = i >> 5, k4 = i & 31;
        int n = n0 + r;
        float4 v = make_float4(0.f, 0.f, 0.f, 0.f);
        if (n < NN) v = reinterpret_cast<const float4*>(g_agg)[(size_t)n * 32 + k4];
        float* p = inS + r * 130 + k4 * 4;
        p[0] = v.x; p[1] = v.y; p[2] = v.z; p[3] = v.w;
    }
    __syncthreads();

    const int ei = tid >> 4;
    const int c0 = (tid & 15) * 8;

    float acc[8][8];
    #pragma unroll
    for (int r = 0; r < 8; r++)
        #pragma unroll
        for (int j = 0; j < 8; j++) acc[r][j] = bs[c0 + j];

    #pragma unroll 2
    for (int k = 0; k < CH; k++) {
        float a[8];
        #pragma unroll
        for (int r = 0; r < 8; r++) a[r] = inS[(ei * 8 + r) * 130 + k];
        float4 w0 = *reinterpret_cast<const float4*>(Ws + k * CH + c0);
        float4 w1 = *reinterpret_cast<const float4*>(Ws + k * CH + c0 + 4);
        #pragma unroll
        for (int r = 0; r < 8; r++) { FMA8(acc[r], a[r], w0, w1); }
    }
    #pragma unroll
    for (int r = 0; r < 8; r++)
        #pragma unroll
        for (int j = 0; j < 8; j++)
            tS[(ei * 8 + r) * 130 + c0 + j] = ssp(acc[r][j]);
    __syncthreads();

    for (int i = tid; i < CH * CH; i += 256) Ws[i] = Wm2[i];
    if (tid < CH) bs[tid] = bm2[tid];
    __syncthreads();

    #pragma unroll
    for (int r = 0; r < 8; r++)
        #pragma unroll
        for (int j = 0; j < 8; j++) acc[r][j] = bs[c0 + j];

    #pragma unroll 2
    for (int k = 0; k < CH; k++) {
        float a[8];
        #pragma unroll
        for (int r = 0; r < 8; r++) a[r] = tS[(ei * 8 + r) * 130 + k];
        float4 w0 = *reinterpret_cast<const float4*>(Ws + k * CH + c0);
        float4 w1 = *reinterpret_cast<const float4*>(Ws + k * CH + c0 + 4);
        #pragma unroll
        for (int r = 0; r < 8; r++) { FMA8(acc[r], a[r], w0, w1); }
    }

    #pragma unroll
    for (int r = 0; r < 8; r++) {
        int n = n0 + ei * 8 + r;
        if (n < NN) {
            float* dst = out + (size_t)n * CH + c0;
            *reinterpret_cast<float4*>(dst)     = make_float4(acc[r][0], acc[r][1], acc[r][2], acc[r][3]);
            *reinterpret_cast<float4*>(dst + 4) = make_float4(acc[r][4], acc[r][5], acc[r][6], acc[r][7]);
        }
    }
}

// ---------------------------------------------------------------------------
extern "C" void kernel_launch(void* const* d_in, const int* in_sizes, int n_in,
                              void* d_out, int out_size)
{
    const float* features = (const float*)d_in[0];
    const float* dist     = (const float*)d_in[1];
    const float* W_lin    = (const float*)d_in[2];
    const float* Wf1      = (const float*)d_in[3];
    const float* bf1      = (const float*)d_in[4];
    const float* Wf2      = (const float*)d_in[5];
    const float* bf2      = (const float*)d_in[6];
    const float* Wm1      = (const float*)d_in[7];
    const float* bm1      = (const float*)d_in[8];
    const float* Wm2      = (const float*)d_in[9];
    const float* bm2      = (const float*)d_in[10];
    const int*   senders   = (const int*)d_in[11];
    const int*   receivers = (const int*)d_in[12];
    float* out = (float*)d_out;

    const int smemA = (CH * TS + 128 * 130) * 4;                                   // node linear
    const int smemT = (FE * CH + CH * CH + 2 * CH + 128 * 53 + 128 * 130) * 4;     // table build
    const int smemC = (CH * CH + CH + 2 * 128 * 130) * 4;                          // out mlp

    cudaFuncSetAttribute(node_linear_kernel, cudaFuncAttributeMaxDynamicSharedMemorySize, smemA);
    cudaFuncSetAttribute(table_kernel,       cudaFuncAttributeMaxDynamicSharedMemorySize, smemT);
    cudaFuncSetAttribute(out_mlp_kernel,     cudaFuncAttributeMaxDynamicSharedMemorySize, smemC);

    zero_agg_kernel<<<1024, 256>>>();
    table_kernel<<<(NTAB + 1 + 127) / 128, 256, smemT>>>(Wf1, bf1, Wf2, bf2);
    node_linear_kernel<<<(NN + 127) / 128, 256, smemA>>>(features, W_lin);
    edge_apply_kernel<<<2048, 256>>>(dist, senders, receivers);
    out_mlp_kernel<<<(NN + 127) / 128, 256, smemC>>>(Wm1, bm1, Wm2, bm2, out);
}